// round 15
// baseline (speedup 1.0000x reference)
#include <cuda_runtime.h>
#include <cuda_fp16.h>
#include <cstdint>
#include <math.h>

#define NROW 8192
#define MROW 8192
#define DDIM 256
#define TILE 128
#define GRID 152
#define NTILES 4096   // 64 rowblocks x 64 coltiles

// Scratch: fp16, PRE-SWIZZLED 64KB blocks of 128 rows:
// block = 4 K-chunks of [128 rows x 64 halves] (128B rows), SW128-swizzled.
__device__ uint4 g_pk[NROW * 32];
__device__ uint4 g_nv[MROW * 32];
__device__ float g_pos[NROW];
__device__ float g_rowsum[NROW];

// ---------------------------------------------------------------------------
__device__ __forceinline__ uint32_t smem_u32(const void* p) {
    uint32_t a;
    asm("{ .reg .u64 t; cvta.to.shared.u64 t, %1; cvt.u32.u64 %0, t; }" : "=r"(a) : "l"(p));
    return a;
}
__device__ __forceinline__ uint32_t elect_one() {
    uint32_t p;
    asm volatile("{\n\t.reg .pred p;\n\telect.sync _|p, 0xFFFFFFFF;\n\tselp.b32 %0,1,0,p;\n\t}" : "=r"(p));
    return p;
}
#define MBAR_INIT(a, c) asm volatile("mbarrier.init.shared.b64 [%0], %1;" :: "r"(a), "r"(c) : "memory")
#define MBAR_EXPECT(a, n) asm volatile("mbarrier.arrive.expect_tx.shared.b64 _, [%0], %1;" :: "r"(a), "r"(n) : "memory")
#define MBAR_WAIT(a, ph) do {                                                           \
    asm volatile("{\n\t.reg .pred P1;\n\t"                                              \
                 "WL%=:\n\t"                                                            \
                 "mbarrier.try_wait.parity.acquire.cta.shared::cta.b64 P1, [%0], %1, 0x989680;\n\t" \
                 "@P1 bra.uni WD%=;\n\t"                                                \
                 "bra.uni WL%=;\n\t"                                                    \
                 "WD%=:\n\t}" :: "r"(a), "r"(ph) : "memory");                           \
} while (0)
#define BULK_LD(dst, src, bytes, mbar) asm volatile( \
    "cp.async.bulk.shared::cluster.global.mbarrier::complete_tx::bytes [%0], [%1], %2, [%3];" \
    :: "r"(dst), "l"(src), "r"(bytes), "r"(mbar) : "memory")

// fp16 in, fp16 accumulate: D/C = 2 regs (f16x2 pairs)
__device__ __forceinline__ void mma_f16(uint32_t* d, const uint32_t* a, uint32_t b0, uint32_t b1) {
    asm volatile(
        "mma.sync.aligned.m16n8k16.row.col.f16.f16.f16.f16 "
        "{%0,%1},{%2,%3,%4,%5},{%6,%7},{%0,%1};\n"
        : "+r"(d[0]), "+r"(d[1])
        : "r"(a[0]), "r"(a[1]), "r"(a[2]), "r"(a[3]), "r"(b0), "r"(b1));
}
__device__ __forceinline__ uint32_t ex2_h2(uint32_t x) {
    uint32_t r;
    asm("ex2.approx.f16x2 %0, %1;" : "=r"(r) : "r"(x));
    return r;
}
__device__ __forceinline__ uint32_t hmul2_u(uint32_t a, uint32_t b) {
    __half2 r = __hmul2(*reinterpret_cast<const __half2*>(&a),
                        *reinterpret_cast<const __half2*>(&b));
    return *reinterpret_cast<uint32_t*>(&r);
}
__device__ __forceinline__ uint32_t hadd2_u(uint32_t a, uint32_t b) {
    __half2 r = __hadd2(*reinterpret_cast<const __half2*>(&a),
                        *reinterpret_cast<const __half2*>(&b));
    return *reinterpret_cast<uint32_t*>(&r);
}

// ---------------------------------------------------------------------------
// Kernel 1: normalize -> fp16, PRE-SWIZZLED tile-block layout, pos_sim, zero.
// (R11-exact, known good.)
// ---------------------------------------------------------------------------
__device__ __forceinline__ void store_sw(uint4* g, int row, int lane, uint4 v) {
    int blk = row >> 7, rowIn = row & 127;
    uint32_t off = (uint32_t)(rowIn * 128 + (lane & 7) * 16);
    off = off ^ ((off >> 3) & 0x70);
    g[blk * 4096 + (lane >> 3) * 1024 + (off >> 4)] = v;
}

__global__ void __launch_bounds__(256) prep_kernel(const float4* __restrict__ pk,
                                                   const float4* __restrict__ pv,
                                                   const float4* __restrict__ nv,
                                                   float* __restrict__ out) {
    const int row = blockIdx.x * 8 + (threadIdx.x >> 5);
    const int lane = threadIdx.x & 31;
    if (blockIdx.x == 0 && threadIdx.x == 0) out[0] = 0.0f;

    if (row < NROW) {
        float4 k0 = pk[row * 64 + 2 * lane], k1 = pk[row * 64 + 2 * lane + 1];
        float4 v0 = pv[row * 64 + 2 * lane], v1 = pv[row * 64 + 2 * lane + 1];
        float ssk = k0.x*k0.x + k0.y*k0.y + k0.z*k0.z + k0.w*k0.w
                  + k1.x*k1.x + k1.y*k1.y + k1.z*k1.z + k1.w*k1.w;
        float ssv = v0.x*v0.x + v0.y*v0.y + v0.z*v0.z + v0.w*v0.w
                  + v1.x*v1.x + v1.y*v1.y + v1.z*v1.z + v1.w*v1.w;
        float dkv = k0.x*v0.x + k0.y*v0.y + k0.z*v0.z + k0.w*v0.w
                  + k1.x*v1.x + k1.y*v1.y + k1.z*v1.z + k1.w*v1.w;
        #pragma unroll
        for (int o = 16; o > 0; o >>= 1) {
            ssk += __shfl_xor_sync(0xffffffffu, ssk, o);
            ssv += __shfl_xor_sync(0xffffffffu, ssv, o);
            dkv += __shfl_xor_sync(0xffffffffu, dkv, o);
        }
        float sk = 1.0f / fmaxf(sqrtf(ssk), 1e-8f);
        float sv = 1.0f / fmaxf(sqrtf(ssv), 1e-8f);
        __half2 h0 = __floats2half2_rn(k0.x*sk, k0.y*sk);
        __half2 h1 = __floats2half2_rn(k0.z*sk, k0.w*sk);
        __half2 h2 = __floats2half2_rn(k1.x*sk, k1.y*sk);
        __half2 h3 = __floats2half2_rn(k1.z*sk, k1.w*sk);
        uint4 u = make_uint4(*(unsigned*)&h0, *(unsigned*)&h1, *(unsigned*)&h2, *(unsigned*)&h3);
        store_sw(g_pk, row, lane, u);
        if (lane == 0) {
            g_pos[row] = dkv * sk * sv;
            g_rowsum[row] = 0.0f;
        }
    } else {
        const int r = row - NROW;
        float4 x0 = nv[r * 64 + 2 * lane], x1 = nv[r * 64 + 2 * lane + 1];
        float ss = x0.x*x0.x + x0.y*x0.y + x0.z*x0.z + x0.w*x0.w
                 + x1.x*x1.x + x1.y*x1.y + x1.z*x1.z + x1.w*x1.w;
        #pragma unroll
        for (int o = 16; o > 0; o >>= 1)
            ss += __shfl_xor_sync(0xffffffffu, ss, o);
        float s = 1.0f / fmaxf(sqrtf(ss), 1e-8f);
        __half2 h0 = __floats2half2_rn(x0.x*s, x0.y*s);
        __half2 h1 = __floats2half2_rn(x0.z*s, x0.w*s);
        __half2 h2 = __floats2half2_rn(x1.x*s, x1.y*s);
        __half2 h3 = __floats2half2_rn(x1.z*s, x1.w*s);
        uint4 u = make_uint4(*(unsigned*)&h0, *(unsigned*)&h1, *(unsigned*)&h2, *(unsigned*)&h3);
        store_sw(g_nv, r, lane, u);
    }
}

// ---------------------------------------------------------------------------
// Kernel 2: fp16 HMMA GEMM + fused LSE.
// NEW: 2-D warp tiling 4(M)x2(N), warp tile 32x64 -> 6 LDSM.x4 per warp per
// k-step (2 A + 4 B) vs 8 before: smem traffic 524KB -> 393KB per tile,
// pulling smem below the MMA floor. A read from smem per k-step (no afr).
// Ping-pong accumulators keep the exp-epilogue hidden in the MMA stream.
// ---------------------------------------------------------------------------
__device__ __forceinline__ void tile_body(
    uint32_t aBase, uint32_t bb,
    const uint32_t (&arb)[2], const uint32_t (&arx)[2], uint32_t lnc,
    const uint32_t (&brb)[4], const uint32_t (&brx)[4],
    uint32_t (&accCur)[2][8][2], const uint32_t (&accPrev)[2][8][2],
    bool doEpi, int epiBase, int lane, uint32_t Ch2) {

    #pragma unroll
    for (int mi = 0; mi < 2; mi++)
        #pragma unroll
        for (int g = 0; g < 8; g++) { accCur[mi][g][0] = 0u; accCur[mi][g][1] = 0u; }

    uint32_t s[2][2] = {{0u, 0u}, {0u, 0u}};   // half2 partial row sums (prev tile)

    #pragma unroll
    for (int ks = 0; ks < 16; ks++) {
        const uint32_t kchA = aBase + ((ks >> 2) << 14);
        const uint32_t kchB = bb + ((ks >> 2) << 14);
        const uint32_t kcol = (uint32_t)((ks & 3) << 5);
        uint32_t a[2][4], b[4][4];
        #pragma unroll
        for (int mi = 0; mi < 2; mi++) {
            uint32_t addr = kchA + arb[mi] + ((kcol | lnc) ^ arx[mi]);
            asm volatile("ldmatrix.sync.aligned.m8n8.x4.shared.b16 {%0,%1,%2,%3},[%4];"
                         : "=r"(a[mi][0]), "=r"(a[mi][1]), "=r"(a[mi][2]), "=r"(a[mi][3])
                         : "r"(addr));
        }
        #pragma unroll
        for (int j = 0; j < 4; j++) {
            uint32_t addr = kchB + brb[j] + (kcol ^ brx[j]);
            asm volatile("ldmatrix.sync.aligned.m8n8.x4.shared.b16 {%0,%1,%2,%3},[%4];"
                         : "=r"(b[j][0]), "=r"(b[j][1]), "=r"(b[j][2]), "=r"(b[j][3])
                         : "r"(addr));
        }
        #pragma unroll
        for (int mi = 0; mi < 2; mi++)
            #pragma unroll
            for (int j = 0; j < 4; j++) {
                mma_f16(accCur[mi][2 * j],     a[mi], b[j][0], b[j][2]);
                mma_f16(accCur[mi][2 * j + 1], a[mi], b[j][1], b[j][3]);
            }
        // deferred epilogue slice for prev tile (2 regs per k-step)
        {
            const int mi = ks >> 3, g = ks & 7;
            s[mi][0] = hadd2_u(s[mi][0], ex2_h2(hmul2_u(accPrev[mi][g][0], Ch2)));
            s[mi][1] = hadd2_u(s[mi][1], ex2_h2(hmul2_u(accPrev[mi][g][1], Ch2)));
        }
    }

    if (doEpi) {
        #pragma unroll
        for (int mi = 0; mi < 2; mi++) {
            float2 f0 = __half22float2(*reinterpret_cast<__half2*>(&s[mi][0]));
            float2 f1 = __half22float2(*reinterpret_cast<__half2*>(&s[mi][1]));
            float r0 = f0.x + f0.y, r1 = f1.x + f1.y;
            r0 += __shfl_xor_sync(0xffffffffu, r0, 1);
            r0 += __shfl_xor_sync(0xffffffffu, r0, 2);
            r1 += __shfl_xor_sync(0xffffffffu, r1, 1);
            r1 += __shfl_xor_sync(0xffffffffu, r1, 2);
            if ((lane & 3) == 0) {
                atomicAdd(&g_rowsum[epiBase + mi * 16], r0);
                atomicAdd(&g_rowsum[epiBase + mi * 16 + 8], r1);
            }
        }
    }
}

__device__ __forceinline__ void epi_only(const uint32_t (&acc)[2][8][2],
                                         int epiBase, int lane, uint32_t Ch2) {
    #pragma unroll
    for (int mi = 0; mi < 2; mi++) {
        uint32_t s0 = 0u, s1 = 0u;
        #pragma unroll
        for (int g = 0; g < 8; g++) {
            s0 = hadd2_u(s0, ex2_h2(hmul2_u(acc[mi][g][0], Ch2)));
            s1 = hadd2_u(s1, ex2_h2(hmul2_u(acc[mi][g][1], Ch2)));
        }
        float2 f0 = __half22float2(*reinterpret_cast<__half2*>(&s0));
        float2 f1 = __half22float2(*reinterpret_cast<__half2*>(&s1));
        float r0 = f0.x + f0.y, r1 = f1.x + f1.y;
        r0 += __shfl_xor_sync(0xffffffffu, r0, 1);
        r0 += __shfl_xor_sync(0xffffffffu, r0, 2);
        r1 += __shfl_xor_sync(0xffffffffu, r1, 1);
        r1 += __shfl_xor_sync(0xffffffffu, r1, 2);
        if ((lane & 3) == 0) {
            atomicAdd(&g_rowsum[epiBase + mi * 16], r0);
            atomicAdd(&g_rowsum[epiBase + mi * 16 + 8], r1);
        }
    }
}

__global__ void __launch_bounds__(256, 1) gemm_lse_kernel() {
    extern __shared__ __align__(1024) char dsmem[];
    __shared__ __align__(8) uint64_t s_mbar[3];   // B0, B1, A

    const int tid = threadIdx.x;
    const int warp = tid >> 5;
    const int lane = tid & 31;
    const int wm = warp & 3;    // warp M index (0..3)
    const int wn = warp >> 2;   // warp N index (0..1)

    uint32_t sb = smem_u32(dsmem);
    const uint32_t aBase = (sb + 1023u) & ~1023u;
    const uint32_t bBase[2] = {aBase + 65536u, aBase + 131072u};
    const uint32_t mbB[2] = {smem_u32(&s_mbar[0]), smem_u32(&s_mbar[1])};
    const uint32_t mbA = smem_u32(&s_mbar[2]);

    if (tid == 0) {
        MBAR_INIT(mbB[0], 1);
        MBAR_INIT(mbB[1], 1);
        MBAR_INIT(mbA, 1);
    }
    __syncthreads();

    const int t_begin = ((int)blockIdx.x * NTILES) / GRID;
    const int t_end = (((int)blockIdx.x + 1) * NTILES) / GRID;

    if (warp == 0 && elect_one()) {
        MBAR_EXPECT(mbA, 65536u);
        BULK_LD(aBase, (const char*)g_pk + (size_t)(t_begin >> 6) * 65536, 65536u, mbA);
        MBAR_EXPECT(mbB[0], 65536u);
        BULK_LD(bBase[0], (const char*)g_nv + (size_t)(t_begin & 63) * 65536, 65536u, mbB[0]);
    }

    // per-lane ldmatrix address components
    const int fr = (lane & 7) + ((lane >> 3) & 1) * 8;   // frag row within 16
    const uint32_t lnc = (uint32_t)((lane >> 4) << 4);
    uint32_t arb[2], arx[2];
    #pragma unroll
    for (int mi = 0; mi < 2; mi++) {
        int r = wm * 32 + mi * 16 + fr;
        arb[mi] = (uint32_t)(r * 128);
        arx[mi] = (uint32_t)((r & 7) << 4);
    }
    uint32_t brb[4], brx[4];
    #pragma unroll
    for (int j = 0; j < 4; j++) {
        int r = wn * 64 + j * 16 + fr;
        brb[j] = (uint32_t)(r * 128);
        brx[j] = (uint32_t)((r & 7) << 4) ^ lnc;
    }

    const __half2 Chh = __half2half2(__float2half(0.72134752044448170f));  // log2(e)/2
    const uint32_t Ch2 = *reinterpret_cast<const uint32_t*>(&Chh);

    uint32_t acc0[2][8][2], acc1[2][8][2];
    #pragma unroll
    for (int mi = 0; mi < 2; mi++)
        #pragma unroll
        for (int g = 0; g < 8; g++) {
            acc0[mi][g][0] = acc0[mi][g][1] = 0u;
            acc1[mi][g][0] = acc1[mi][g][1] = 0u;
        }

    int curRb = -1, phA = 0, prevRb = 0;

    for (int t = t_begin, k = 0; t < t_end; t++, k++) {
        const int rb = t >> 6;
        __syncthreads();   // prev tile done: B[(k+1)&1] and (old) A smem free
        if (rb != curRb) {
            if (curRb >= 0 && warp == 0 && elect_one()) {
                MBAR_EXPECT(mbA, 65536u);
                BULK_LD(aBase, (const char*)g_pk + (size_t)rb * 65536, 65536u, mbA);
            }
            MBAR_WAIT(mbA, phA);
            phA ^= 1;
            curRb = rb;
        }

        const int tn = t + 1;
        if (tn < t_end && warp == 0 && elect_one()) {
            MBAR_EXPECT(mbB[(k + 1) & 1], 65536u);
            BULK_LD(bBase[(k + 1) & 1],
                    (const char*)g_nv + (size_t)(tn & 63) * 65536, 65536u, mbB[(k + 1) & 1]);
        }
        MBAR_WAIT(mbB[k & 1], (k >> 1) & 1);

        const uint32_t bb = bBase[k & 1];
        const bool doEpi = (k > 0);
        const int epiBase = prevRb * TILE + wm * 32 + (lane >> 2);
        if (k & 1)
            tile_body(aBase, bb, arb, arx, lnc, brb, brx, acc1, acc0, doEpi, epiBase, lane, Ch2);
        else
            tile_body(aBase, bb, arb, arx, lnc, brb, brx, acc0, acc1, doEpi, epiBase, lane, Ch2);
        prevRb = rb;
    }

    // epilogue for the final tile
    const int epiBase = prevRb * TILE + wm * 32 + (lane >> 2);
    if ((t_end - t_begin - 1) & 1)
        epi_only(acc1, epiBase, lane, Ch2);
    else
        epi_only(acc0, epiBase, lane, Ch2);
}

// ---------------------------------------------------------------------------
// Kernel 3: parallel final reduction (R11-exact).
// ---------------------------------------------------------------------------
__global__ void __launch_bounds__(256) reduce_kernel(float* __restrict__ out) {
    __shared__ float sv[8];
    const int tid = threadIdx.x;
    const int r = blockIdx.x * 256 + tid;
    float v = __logf(g_rowsum[r]) - 0.5f * g_pos[r];
    #pragma unroll
    for (int o = 16; o > 0; o >>= 1)
        v += __shfl_xor_sync(0xffffffffu, v, o);
    const int lane = tid & 31, warp = tid >> 5;
    if (lane == 0) sv[warp] = v;
    __syncthreads();
    if (warp == 0) {
        v = (lane < 8) ? sv[lane] : 0.0f;
        #pragma unroll
        for (int o = 4; o > 0; o >>= 1)
            v += __shfl_xor_sync(0xffffffffu, v, o);
        if (lane == 0)
            atomicAdd(out, v * (1.0f / NROW));
    }
}

// ---------------------------------------------------------------------------
extern "C" void kernel_launch(void* const* d_in, const int* in_sizes, int n_in,
                              void* d_out, int out_size) {
    const float4* pk = reinterpret_cast<const float4*>(d_in[0]);
    const float4* pv = reinterpret_cast<const float4*>(d_in[1]);
    const float4* nv = reinterpret_cast<const float4*>(d_in[2]);
    float* out = reinterpret_cast<float*>(d_out);

    const int smem_bytes = 1024 + 3 * 65536;  // pad + A + 2x B
    cudaFuncSetAttribute(gemm_lse_kernel,
                         cudaFuncAttributeMaxDynamicSharedMemorySize, smem_bytes);

    prep_kernel<<<(NROW + MROW) / 8, 256>>>(pk, pv, nv, out);
    gemm_lse_kernel<<<GRID, 256, smem_bytes>>>();
    reduce_kernel<<<32, 256>>>(out);
}

// round 16
// speedup vs baseline: 1.5027x; 1.5027x over previous
#include <cuda_runtime.h>
#include <cuda_fp16.h>
#include <cstdint>
#include <math.h>

#define NROW 8192
#define MROW 8192
#define DDIM 256
#define TILE 128
#define GRID 152
#define NTILES 4096   // 64 rowblocks x 64 coltiles

// Scratch: fp16, PRE-SWIZZLED 64KB blocks of 128 rows:
// block = 4 K-chunks of [128 rows x 64 halves] (128B rows), SW128-swizzled.
__device__ uint4 g_pk[NROW * 32];
__device__ uint4 g_nv[MROW * 32];
__device__ float g_pos[NROW];
__device__ float g_rowsum[NROW];

// ---------------------------------------------------------------------------
__device__ __forceinline__ uint32_t smem_u32(const void* p) {
    uint32_t a;
    asm("{ .reg .u64 t; cvta.to.shared.u64 t, %1; cvt.u32.u64 %0, t; }" : "=r"(a) : "l"(p));
    return a;
}
__device__ __forceinline__ uint32_t elect_one() {
    uint32_t p;
    asm volatile("{\n\t.reg .pred p;\n\telect.sync _|p, 0xFFFFFFFF;\n\tselp.b32 %0,1,0,p;\n\t}" : "=r"(p));
    return p;
}
#define MBAR_INIT(a, c) asm volatile("mbarrier.init.shared.b64 [%0], %1;" :: "r"(a), "r"(c) : "memory")
#define MBAR_EXPECT(a, n) asm volatile("mbarrier.arrive.expect_tx.shared.b64 _, [%0], %1;" :: "r"(a), "r"(n) : "memory")
#define MBAR_WAIT(a, ph) do {                                                           \
    asm volatile("{\n\t.reg .pred P1;\n\t"                                              \
                 "WL%=:\n\t"                                                            \
                 "mbarrier.try_wait.parity.acquire.cta.shared::cta.b64 P1, [%0], %1, 0x989680;\n\t" \
                 "@P1 bra.uni WD%=;\n\t"                                                \
                 "bra.uni WL%=;\n\t"                                                    \
                 "WD%=:\n\t}" :: "r"(a), "r"(ph) : "memory");                           \
} while (0)
#define BULK_LD(dst, src, bytes, mbar) asm volatile( \
    "cp.async.bulk.shared::cluster.global.mbarrier::complete_tx::bytes [%0], [%1], %2, [%3];" \
    :: "r"(dst), "l"(src), "r"(bytes), "r"(mbar) : "memory")

// fp16 in, fp16 accumulate: D/C = 2 regs (f16x2 pairs)
__device__ __forceinline__ void mma_f16(uint32_t* d, const uint32_t* a, uint32_t b0, uint32_t b1) {
    asm volatile(
        "mma.sync.aligned.m16n8k16.row.col.f16.f16.f16.f16 "
        "{%0,%1},{%2,%3,%4,%5},{%6,%7},{%0,%1};\n"
        : "+r"(d[0]), "+r"(d[1])
        : "r"(a[0]), "r"(a[1]), "r"(a[2]), "r"(a[3]), "r"(b0), "r"(b1));
}
__device__ __forceinline__ uint32_t ex2_h2(uint32_t x) {
    uint32_t r;
    asm("ex2.approx.f16x2 %0, %1;" : "=r"(r) : "r"(x));
    return r;
}
__device__ __forceinline__ uint32_t hmul2_u(uint32_t a, uint32_t b) {
    __half2 r = __hmul2(*reinterpret_cast<const __half2*>(&a),
                        *reinterpret_cast<const __half2*>(&b));
    return *reinterpret_cast<uint32_t*>(&r);
}
__device__ __forceinline__ uint32_t hadd2_u(uint32_t a, uint32_t b) {
    __half2 r = __hadd2(*reinterpret_cast<const __half2*>(&a),
                        *reinterpret_cast<const __half2*>(&b));
    return *reinterpret_cast<uint32_t*>(&r);
}
// 256-bit global load (sm_100+): 8 consecutive floats
__device__ __forceinline__ void ldg_v8(const float* p, float* o) {
    asm("ld.global.v8.f32 {%0,%1,%2,%3,%4,%5,%6,%7}, [%8];"
        : "=f"(o[0]), "=f"(o[1]), "=f"(o[2]), "=f"(o[3]),
          "=f"(o[4]), "=f"(o[5]), "=f"(o[6]), "=f"(o[7])
        : "l"(p));
}

// ---------------------------------------------------------------------------
// Kernel 1: normalize -> fp16, PRE-SWIZZLED tile-block layout, pos_sim, zero.
// Lane L owns elems [8L, 8L+8): ONE full-density v8 load per tensor; store
// mapping byte-identical to the proven R11 layout.
// ---------------------------------------------------------------------------
__device__ __forceinline__ void store_sw(uint4* g, int row, int lane, uint4 v) {
    int blk = row >> 7, rowIn = row & 127;
    uint32_t off = (uint32_t)(rowIn * 128 + (lane & 7) * 16);
    off = off ^ ((off >> 3) & 0x70);
    g[blk * 4096 + (lane >> 3) * 1024 + (off >> 4)] = v;
}

__global__ void __launch_bounds__(256) prep_kernel(const float* __restrict__ pk,
                                                   const float* __restrict__ pv,
                                                   const float* __restrict__ nv,
                                                   float* __restrict__ out) {
    const int row = blockIdx.x * 8 + (threadIdx.x >> 5);
    const int lane = threadIdx.x & 31;
    if (blockIdx.x == 0 && threadIdx.x == 0) out[0] = 0.0f;

    if (row < NROW) {
        float k[8], v[8];
        ldg_v8(pk + (size_t)row * DDIM + lane * 8, k);
        ldg_v8(pv + (size_t)row * DDIM + lane * 8, v);
        float ssk = 0.0f, ssv = 0.0f, dkv = 0.0f;
        #pragma unroll
        for (int i = 0; i < 8; i++) {
            ssk += k[i] * k[i];
            ssv += v[i] * v[i];
            dkv += k[i] * v[i];
        }
        #pragma unroll
        for (int o = 16; o > 0; o >>= 1) {
            ssk += __shfl_xor_sync(0xffffffffu, ssk, o);
            ssv += __shfl_xor_sync(0xffffffffu, ssv, o);
            dkv += __shfl_xor_sync(0xffffffffu, dkv, o);
        }
        float sk = 1.0f / fmaxf(sqrtf(ssk), 1e-8f);
        float sv = 1.0f / fmaxf(sqrtf(ssv), 1e-8f);
        __half2 h0 = __floats2half2_rn(k[0]*sk, k[1]*sk);
        __half2 h1 = __floats2half2_rn(k[2]*sk, k[3]*sk);
        __half2 h2 = __floats2half2_rn(k[4]*sk, k[5]*sk);
        __half2 h3 = __floats2half2_rn(k[6]*sk, k[7]*sk);
        uint4 u = make_uint4(*(unsigned*)&h0, *(unsigned*)&h1, *(unsigned*)&h2, *(unsigned*)&h3);
        store_sw(g_pk, row, lane, u);
        if (lane == 0) {
            g_pos[row] = dkv * sk * sv;
            g_rowsum[row] = 0.0f;
        }
    } else {
        const int r = row - NROW;
        float x[8];
        ldg_v8(nv + (size_t)r * DDIM + lane * 8, x);
        float ss = 0.0f;
        #pragma unroll
        for (int i = 0; i < 8; i++) ss += x[i] * x[i];
        #pragma unroll
        for (int o = 16; o > 0; o >>= 1)
            ss += __shfl_xor_sync(0xffffffffu, ss, o);
        float s = 1.0f / fmaxf(sqrtf(ss), 1e-8f);
        __half2 h0 = __floats2half2_rn(x[0]*s, x[1]*s);
        __half2 h1 = __floats2half2_rn(x[2]*s, x[3]*s);
        __half2 h2 = __floats2half2_rn(x[4]*s, x[5]*s);
        __half2 h3 = __floats2half2_rn(x[6]*s, x[7]*s);
        uint4 u = make_uint4(*(unsigned*)&h0, *(unsigned*)&h1, *(unsigned*)&h2, *(unsigned*)&h3);
        store_sw(g_nv, r, lane, u);
    }
}

// ---------------------------------------------------------------------------
// Kernel 2: fp16 HMMA GEMM + fused LSE (proven R7/R11 mainloop, UNCHANGED).
// ---------------------------------------------------------------------------
__device__ __forceinline__ void tile_body(
    uint32_t bb, const uint32_t (&afr)[16][4],
    const uint32_t (&brb)[8], const uint32_t (&brx)[8],
    uint32_t (&accCur)[16][2], const uint32_t (&accPrev)[16][2],
    bool doEpi, int epiRow, int lane, uint32_t Ch2) {

    #pragma unroll
    for (int g = 0; g < 16; g++) { accCur[g][0] = 0u; accCur[g][1] = 0u; }

    uint32_t s0 = 0u, s1 = 0u;   // half2 partial row sums (prev tile)

    #pragma unroll
    for (int ks = 0; ks < 16; ks++) {
        const uint32_t kch = bb + ((ks >> 2) << 14);
        const uint32_t kcol = (uint32_t)((ks & 3) << 5);
        uint32_t b[8][4];
        #pragma unroll
        for (int j = 0; j < 8; j++) {
            uint32_t addr = kch + brb[j] + (kcol ^ brx[j]);
            asm volatile("ldmatrix.sync.aligned.m8n8.x4.shared.b16 {%0,%1,%2,%3},[%4];"
                         : "=r"(b[j][0]), "=r"(b[j][1]), "=r"(b[j][2]), "=r"(b[j][3])
                         : "r"(addr));
        }
        #pragma unroll
        for (int j = 0; j < 8; j++) {
            mma_f16(accCur[2 * j],     afr[ks], b[j][0], b[j][2]);
            mma_f16(accCur[2 * j + 1], afr[ks], b[j][1], b[j][3]);
        }
        // deferred epilogue slice for prev tile (independent regs)
        s0 = hadd2_u(s0, ex2_h2(hmul2_u(accPrev[ks][0], Ch2)));
        s1 = hadd2_u(s1, ex2_h2(hmul2_u(accPrev[ks][1], Ch2)));
    }

    if (doEpi) {
        float2 f0 = __half22float2(*reinterpret_cast<__half2*>(&s0));
        float2 f1 = __half22float2(*reinterpret_cast<__half2*>(&s1));
        float r0 = f0.x + f0.y, r1 = f1.x + f1.y;
        r0 += __shfl_xor_sync(0xffffffffu, r0, 1);
        r0 += __shfl_xor_sync(0xffffffffu, r0, 2);
        r1 += __shfl_xor_sync(0xffffffffu, r1, 1);
        r1 += __shfl_xor_sync(0xffffffffu, r1, 2);
        if ((lane & 3) == 0) {
            atomicAdd(&g_rowsum[epiRow], r0);
            atomicAdd(&g_rowsum[epiRow + 8], r1);
        }
    }
}

__device__ __forceinline__ void epi_only(const uint32_t (&acc)[16][2],
                                         int epiRow, int lane, uint32_t Ch2) {
    uint32_t s0 = 0u, s1 = 0u;
    #pragma unroll
    for (int g = 0; g < 16; g++) {
        s0 = hadd2_u(s0, ex2_h2(hmul2_u(acc[g][0], Ch2)));
        s1 = hadd2_u(s1, ex2_h2(hmul2_u(acc[g][1], Ch2)));
    }
    float2 f0 = __half22float2(*reinterpret_cast<__half2*>(&s0));
    float2 f1 = __half22float2(*reinterpret_cast<__half2*>(&s1));
    float r0 = f0.x + f0.y, r1 = f1.x + f1.y;
    r0 += __shfl_xor_sync(0xffffffffu, r0, 1);
    r0 += __shfl_xor_sync(0xffffffffu, r0, 2);
    r1 += __shfl_xor_sync(0xffffffffu, r1, 1);
    r1 += __shfl_xor_sync(0xffffffffu, r1, 2);
    if ((lane & 3) == 0) {
        atomicAdd(&g_rowsum[epiRow], r0);
        atomicAdd(&g_rowsum[epiRow + 8], r1);
    }
}

__global__ void __launch_bounds__(256, 1) gemm_lse_kernel() {
    extern __shared__ __align__(1024) char dsmem[];
    __shared__ __align__(8) uint64_t s_mbar[3];   // B0, B1, A

    const int tid = threadIdx.x;
    const int warp = tid >> 5;
    const int lane = tid & 31;

    uint32_t sb = smem_u32(dsmem);
    const uint32_t aBase = (sb + 1023u) & ~1023u;
    const uint32_t bBase[2] = {aBase + 65536u, aBase + 131072u};
    const uint32_t mbB[2] = {smem_u32(&s_mbar[0]), smem_u32(&s_mbar[1])};
    const uint32_t mbA = smem_u32(&s_mbar[2]);

    if (tid == 0) {
        MBAR_INIT(mbB[0], 1);
        MBAR_INIT(mbB[1], 1);
        MBAR_INIT(mbA, 1);
    }
    __syncthreads();

    const int t_begin = ((int)blockIdx.x * NTILES) / GRID;
    const int t_end = (((int)blockIdx.x + 1) * NTILES) / GRID;

    if (warp == 0 && elect_one()) {
        MBAR_EXPECT(mbA, 65536u);
        BULK_LD(aBase, (const char*)g_pk + (size_t)(t_begin >> 6) * 65536, 65536u, mbA);
        MBAR_EXPECT(mbB[0], 65536u);
        BULK_LD(bBase[0], (const char*)g_nv + (size_t)(t_begin & 63) * 65536, 65536u, mbB[0]);
    }

    const int arow = warp * 16 + (lane & 7) + ((lane >> 3) & 1) * 8;
    const uint32_t a_rx = (uint32_t)((arow & 7) << 4);
    const uint32_t a_rb = (uint32_t)(arow * 128);
    const uint32_t lnc = (uint32_t)((lane >> 4) << 4);
    uint32_t brb[8], brx[8];
    {
        const int nr = (lane & 7) + ((lane >> 3) & 1) * 8;
        #pragma unroll
        for (int j = 0; j < 8; j++) {
            int r = j * 16 + nr;
            brb[j] = (uint32_t)(r * 128);
            brx[j] = (uint32_t)((r & 7) << 4) ^ lnc;
        }
    }

    const __half2 Chh = __half2half2(__float2half(0.72134752044448170f));  // log2(e)/2
    const uint32_t Ch2 = *reinterpret_cast<const uint32_t*>(&Chh);

    uint32_t afr[16][4];
    uint32_t acc0[16][2], acc1[16][2];
    #pragma unroll
    for (int g = 0; g < 16; g++) {
        acc0[g][0] = acc0[g][1] = 0u;
        acc1[g][0] = acc1[g][1] = 0u;
    }

    int curRb = -1, phA = 0, prevRb = 0;

    for (int t = t_begin, k = 0; t < t_end; t++, k++) {
        const int rb = t >> 6;
        if (rb != curRb) {
            MBAR_WAIT(mbA, phA);
            phA ^= 1;
            #pragma unroll
            for (int ks = 0; ks < 16; ks++) {
                uint32_t addr = aBase + ((ks >> 2) << 14) + a_rb
                              + ((((uint32_t)(ks & 3) << 5) | lnc) ^ a_rx);
                asm volatile("ldmatrix.sync.aligned.m8n8.x4.shared.b16 {%0,%1,%2,%3},[%4];"
                             : "=r"(afr[ks][0]), "=r"(afr[ks][1]), "=r"(afr[ks][2]), "=r"(afr[ks][3])
                             : "r"(addr));
            }
            curRb = rb;
        }
        __syncthreads();   // all warps done with B[(k+1)&1] and A extraction

        const int tn = t + 1;
        if (tn < t_end && warp == 0 && elect_one()) {
            MBAR_EXPECT(mbB[(k + 1) & 1], 65536u);
            BULK_LD(bBase[(k + 1) & 1],
                    (const char*)g_nv + (size_t)(tn & 63) * 65536, 65536u, mbB[(k + 1) & 1]);
            if ((tn >> 6) != rb) {
                MBAR_EXPECT(mbA, 65536u);
                BULK_LD(aBase, (const char*)g_pk + (size_t)(tn >> 6) * 65536, 65536u, mbA);
            }
        }
        MBAR_WAIT(mbB[k & 1], (k >> 1) & 1);

        const uint32_t bb = bBase[k & 1];
        const bool doEpi = (k > 0);
        const int epiRow = prevRb * TILE + warp * 16 + (lane >> 2);
        if (k & 1)
            tile_body(bb, afr, brb, brx, acc1, acc0, doEpi, epiRow, lane, Ch2);
        else
            tile_body(bb, afr, brb, brx, acc0, acc1, doEpi, epiRow, lane, Ch2);
        prevRb = rb;
    }

    // epilogue for the final tile
    const int epiRow = prevRb * TILE + warp * 16 + (lane >> 2);
    if ((t_end - t_begin - 1) & 1)
        epi_only(acc1, epiRow, lane, Ch2);
    else
        epi_only(acc0, epiRow, lane, Ch2);
}

// ---------------------------------------------------------------------------
// Kernel 3: parallel final reduction (R11-exact).
// ---------------------------------------------------------------------------
__global__ void __launch_bounds__(256) reduce_kernel(float* __restrict__ out) {
    __shared__ float sv[8];
    const int tid = threadIdx.x;
    const int r = blockIdx.x * 256 + tid;
    float v = __logf(g_rowsum[r]) - 0.5f * g_pos[r];
    #pragma unroll
    for (int o = 16; o > 0; o >>= 1)
        v += __shfl_xor_sync(0xffffffffu, v, o);
    const int lane = tid & 31, warp = tid >> 5;
    if (lane == 0) sv[warp] = v;
    __syncthreads();
    if (warp == 0) {
        v = (lane < 8) ? sv[lane] : 0.0f;
        #pragma unroll
        for (int o = 4; o > 0; o >>= 1)
            v += __shfl_xor_sync(0xffffffffu, v, o);
        if (lane == 0)
            atomicAdd(out, v * (1.0f / NROW));
    }
}

// ---------------------------------------------------------------------------
extern "C" void kernel_launch(void* const* d_in, const int* in_sizes, int n_in,
                              void* d_out, int out_size) {
    const float* pk = reinterpret_cast<const float*>(d_in[0]);
    const float* pv = reinterpret_cast<const float*>(d_in[1]);
    const float* nv = reinterpret_cast<const float*>(d_in[2]);
    float* out = reinterpret_cast<float*>(d_out);

    const int smem_bytes = 1024 + 3 * 65536;  // pad + A + 2x B
    cudaFuncSetAttribute(gemm_lse_kernel,
                         cudaFuncAttributeMaxDynamicSharedMemorySize, smem_bytes);

    prep_kernel<<<(NROW + MROW) / 8, 256>>>(pk, pv, nv, out);
    gemm_lse_kernel<<<GRID, 256, smem_bytes>>>();
    reduce_kernel<<<32, 256>>>(out);
}

// round 17
// speedup vs baseline: 1.5037x; 1.0007x over previous
#include <cuda_runtime.h>
#include <cuda_fp16.h>
#include <cstdint>
#include <math.h>

#define NROW 8192
#define MROW 8192
#define DDIM 256
#define TILE 128
#define GRID 152
#define NTILES 4096   // 64 rowblocks x 64 coltiles

// Scratch: fp16, PRE-SWIZZLED 64KB blocks of 128 rows:
// block = 4 K-chunks of [128 rows x 64 halves] (128B rows), SW128-swizzled.
__device__ uint4 g_pk[NROW * 32];
__device__ uint4 g_nv[MROW * 32];
__device__ float g_pos[NROW];
__device__ float g_rowsum[NROW];

// ---------------------------------------------------------------------------
__device__ __forceinline__ uint32_t smem_u32(const void* p) {
    uint32_t a;
    asm("{ .reg .u64 t; cvta.to.shared.u64 t, %1; cvt.u32.u64 %0, t; }" : "=r"(a) : "l"(p));
    return a;
}
__device__ __forceinline__ uint32_t elect_one() {
    uint32_t p;
    asm volatile("{\n\t.reg .pred p;\n\telect.sync _|p, 0xFFFFFFFF;\n\tselp.b32 %0,1,0,p;\n\t}" : "=r"(p));
    return p;
}
#define MBAR_INIT(a, c) asm volatile("mbarrier.init.shared.b64 [%0], %1;" :: "r"(a), "r"(c) : "memory")
#define MBAR_EXPECT(a, n) asm volatile("mbarrier.arrive.expect_tx.shared.b64 _, [%0], %1;" :: "r"(a), "r"(n) : "memory")
#define MBAR_WAIT(a, ph) do {                                                           \
    asm volatile("{\n\t.reg .pred P1;\n\t"                                              \
                 "WL%=:\n\t"                                                            \
                 "mbarrier.try_wait.parity.acquire.cta.shared::cta.b64 P1, [%0], %1, 0x989680;\n\t" \
                 "@P1 bra.uni WD%=;\n\t"                                                \
                 "bra.uni WL%=;\n\t"                                                    \
                 "WD%=:\n\t}" :: "r"(a), "r"(ph) : "memory");                           \
} while (0)
#define BULK_LD(dst, src, bytes, mbar) asm volatile( \
    "cp.async.bulk.shared::cluster.global.mbarrier::complete_tx::bytes [%0], [%1], %2, [%3];" \
    :: "r"(dst), "l"(src), "r"(bytes), "r"(mbar) : "memory")

// fp16 in, fp16 accumulate: D/C = 2 regs (f16x2 pairs)
__device__ __forceinline__ void mma_f16(uint32_t* d, const uint32_t* a, uint32_t b0, uint32_t b1) {
    asm volatile(
        "mma.sync.aligned.m16n8k16.row.col.f16.f16.f16.f16 "
        "{%0,%1},{%2,%3,%4,%5},{%6,%7},{%0,%1};\n"
        : "+r"(d[0]), "+r"(d[1])
        : "r"(a[0]), "r"(a[1]), "r"(a[2]), "r"(a[3]), "r"(b0), "r"(b1));
}
__device__ __forceinline__ uint32_t ex2_h2(uint32_t x) {
    uint32_t r;
    asm("ex2.approx.f16x2 %0, %1;" : "=r"(r) : "r"(x));
    return r;
}
__device__ __forceinline__ uint32_t hmul2_u(uint32_t a, uint32_t b) {
    __half2 r = __hmul2(*reinterpret_cast<const __half2*>(&a),
                        *reinterpret_cast<const __half2*>(&b));
    return *reinterpret_cast<uint32_t*>(&r);
}
__device__ __forceinline__ uint32_t hadd2_u(uint32_t a, uint32_t b) {
    __half2 r = __hadd2(*reinterpret_cast<const __half2*>(&a),
                        *reinterpret_cast<const __half2*>(&b));
    return *reinterpret_cast<uint32_t*>(&r);
}
// 256-bit global load (sm_100+): 8 consecutive floats
__device__ __forceinline__ void ldg_v8(const float* p, float* o) {
    asm("ld.global.v8.f32 {%0,%1,%2,%3,%4,%5,%6,%7}, [%8];"
        : "=f"(o[0]), "=f"(o[1]), "=f"(o[2]), "=f"(o[3]),
          "=f"(o[4]), "=f"(o[5]), "=f"(o[6]), "=f"(o[7])
        : "l"(p));
}

// ---------------------------------------------------------------------------
// Kernel 1: normalize -> fp16, PRE-SWIZZLED tile-block layout, pos_sim, zero.
// TWO rows per warp: all v8 loads issued up-front (MLP 4), the two rows'
// shuffle-reduce chains interleave for 2-way ILP. Store mapping (16B
// store_sw) byte-identical to the proven layout.
// ---------------------------------------------------------------------------
__device__ __forceinline__ void store_sw(uint4* g, int row, int lane, uint4 v) {
    int blk = row >> 7, rowIn = row & 127;
    uint32_t off = (uint32_t)(rowIn * 128 + (lane & 7) * 16);
    off = off ^ ((off >> 3) & 0x70);
    g[blk * 4096 + (lane >> 3) * 1024 + (off >> 4)] = v;
}
__device__ __forceinline__ uint4 pack_h8(const float* x, float s) {
    __half2 h0 = __floats2half2_rn(x[0]*s, x[1]*s);
    __half2 h1 = __floats2half2_rn(x[2]*s, x[3]*s);
    __half2 h2 = __floats2half2_rn(x[4]*s, x[5]*s);
    __half2 h3 = __floats2half2_rn(x[6]*s, x[7]*s);
    return make_uint4(*(unsigned*)&h0, *(unsigned*)&h1, *(unsigned*)&h2, *(unsigned*)&h3);
}

__global__ void __launch_bounds__(256) prep_kernel(const float* __restrict__ pk,
                                                   const float* __restrict__ pv,
                                                   const float* __restrict__ nv,
                                                   float* __restrict__ out) {
    const int warp = threadIdx.x >> 5;
    const int lane = threadIdx.x & 31;
    const int r0 = blockIdx.x * 16 + warp * 2;   // rows r0, r0+1 (same branch region)
    if (blockIdx.x == 0 && threadIdx.x == 0) out[0] = 0.0f;

    if (r0 < NROW) {
        float k0[8], v0[8], k1[8], v1[8];
        ldg_v8(pk + (size_t)r0 * DDIM + lane * 8, k0);
        ldg_v8(pv + (size_t)r0 * DDIM + lane * 8, v0);
        ldg_v8(pk + (size_t)(r0 + 1) * DDIM + lane * 8, k1);
        ldg_v8(pv + (size_t)(r0 + 1) * DDIM + lane * 8, v1);
        float sk0 = 0.f, sv0 = 0.f, d0 = 0.f, sk1 = 0.f, sv1 = 0.f, d1 = 0.f;
        #pragma unroll
        for (int i = 0; i < 8; i++) {
            sk0 += k0[i] * k0[i]; sv0 += v0[i] * v0[i]; d0 += k0[i] * v0[i];
            sk1 += k1[i] * k1[i]; sv1 += v1[i] * v1[i]; d1 += k1[i] * v1[i];
        }
        #pragma unroll
        for (int o = 16; o > 0; o >>= 1) {
            sk0 += __shfl_xor_sync(0xffffffffu, sk0, o);
            sk1 += __shfl_xor_sync(0xffffffffu, sk1, o);
            sv0 += __shfl_xor_sync(0xffffffffu, sv0, o);
            sv1 += __shfl_xor_sync(0xffffffffu, sv1, o);
            d0  += __shfl_xor_sync(0xffffffffu, d0, o);
            d1  += __shfl_xor_sync(0xffffffffu, d1, o);
        }
        float a0 = 1.0f / fmaxf(sqrtf(sk0), 1e-8f);
        float b0 = 1.0f / fmaxf(sqrtf(sv0), 1e-8f);
        float a1 = 1.0f / fmaxf(sqrtf(sk1), 1e-8f);
        float b1 = 1.0f / fmaxf(sqrtf(sv1), 1e-8f);
        store_sw(g_pk, r0,     lane, pack_h8(k0, a0));
        store_sw(g_pk, r0 + 1, lane, pack_h8(k1, a1));
        if (lane == 0) {
            g_pos[r0] = d0 * a0 * b0;
            g_pos[r0 + 1] = d1 * a1 * b1;
            g_rowsum[r0] = 0.0f;
            g_rowsum[r0 + 1] = 0.0f;
        }
    } else {
        const int r = r0 - NROW;
        float x0[8], x1[8];
        ldg_v8(nv + (size_t)r * DDIM + lane * 8, x0);
        ldg_v8(nv + (size_t)(r + 1) * DDIM + lane * 8, x1);
        float s0 = 0.f, s1 = 0.f;
        #pragma unroll
        for (int i = 0; i < 8; i++) { s0 += x0[i] * x0[i]; s1 += x1[i] * x1[i]; }
        #pragma unroll
        for (int o = 16; o > 0; o >>= 1) {
            s0 += __shfl_xor_sync(0xffffffffu, s0, o);
            s1 += __shfl_xor_sync(0xffffffffu, s1, o);
        }
        float a0 = 1.0f / fmaxf(sqrtf(s0), 1e-8f);
        float a1 = 1.0f / fmaxf(sqrtf(s1), 1e-8f);
        store_sw(g_nv, r,     lane, pack_h8(x0, a0));
        store_sw(g_nv, r + 1, lane, pack_h8(x1, a1));
    }
}

// ---------------------------------------------------------------------------
// Kernel 2: fp16 HMMA GEMM + fused LSE (proven R7/R11 mainloop, UNCHANGED).
// ---------------------------------------------------------------------------
__device__ __forceinline__ void tile_body(
    uint32_t bb, const uint32_t (&afr)[16][4],
    const uint32_t (&brb)[8], const uint32_t (&brx)[8],
    uint32_t (&accCur)[16][2], const uint32_t (&accPrev)[16][2],
    bool doEpi, int epiRow, int lane, uint32_t Ch2) {

    #pragma unroll
    for (int g = 0; g < 16; g++) { accCur[g][0] = 0u; accCur[g][1] = 0u; }

    uint32_t s0 = 0u, s1 = 0u;   // half2 partial row sums (prev tile)

    #pragma unroll
    for (int ks = 0; ks < 16; ks++) {
        const uint32_t kch = bb + ((ks >> 2) << 14);
        const uint32_t kcol = (uint32_t)((ks & 3) << 5);
        uint32_t b[8][4];
        #pragma unroll
        for (int j = 0; j < 8; j++) {
            uint32_t addr = kch + brb[j] + (kcol ^ brx[j]);
            asm volatile("ldmatrix.sync.aligned.m8n8.x4.shared.b16 {%0,%1,%2,%3},[%4];"
                         : "=r"(b[j][0]), "=r"(b[j][1]), "=r"(b[j][2]), "=r"(b[j][3])
                         : "r"(addr));
        }
        #pragma unroll
        for (int j = 0; j < 8; j++) {
            mma_f16(accCur[2 * j],     afr[ks], b[j][0], b[j][2]);
            mma_f16(accCur[2 * j + 1], afr[ks], b[j][1], b[j][3]);
        }
        // deferred epilogue slice for prev tile (independent regs)
        s0 = hadd2_u(s0, ex2_h2(hmul2_u(accPrev[ks][0], Ch2)));
        s1 = hadd2_u(s1, ex2_h2(hmul2_u(accPrev[ks][1], Ch2)));
    }

    if (doEpi) {
        float2 f0 = __half22float2(*reinterpret_cast<__half2*>(&s0));
        float2 f1 = __half22float2(*reinterpret_cast<__half2*>(&s1));
        float r0 = f0.x + f0.y, r1 = f1.x + f1.y;
        r0 += __shfl_xor_sync(0xffffffffu, r0, 1);
        r0 += __shfl_xor_sync(0xffffffffu, r0, 2);
        r1 += __shfl_xor_sync(0xffffffffu, r1, 1);
        r1 += __shfl_xor_sync(0xffffffffu, r1, 2);
        if ((lane & 3) == 0) {
            atomicAdd(&g_rowsum[epiRow], r0);
            atomicAdd(&g_rowsum[epiRow + 8], r1);
        }
    }
}

__device__ __forceinline__ void epi_only(const uint32_t (&acc)[16][2],
                                         int epiRow, int lane, uint32_t Ch2) {
    uint32_t s0 = 0u, s1 = 0u;
    #pragma unroll
    for (int g = 0; g < 16; g++) {
        s0 = hadd2_u(s0, ex2_h2(hmul2_u(acc[g][0], Ch2)));
        s1 = hadd2_u(s1, ex2_h2(hmul2_u(acc[g][1], Ch2)));
    }
    float2 f0 = __half22float2(*reinterpret_cast<__half2*>(&s0));
    float2 f1 = __half22float2(*reinterpret_cast<__half2*>(&s1));
    float r0 = f0.x + f0.y, r1 = f1.x + f1.y;
    r0 += __shfl_xor_sync(0xffffffffu, r0, 1);
    r0 += __shfl_xor_sync(0xffffffffu, r0, 2);
    r1 += __shfl_xor_sync(0xffffffffu, r1, 1);
    r1 += __shfl_xor_sync(0xffffffffu, r1, 2);
    if ((lane & 3) == 0) {
        atomicAdd(&g_rowsum[epiRow], r0);
        atomicAdd(&g_rowsum[epiRow + 8], r1);
    }
}

__global__ void __launch_bounds__(256, 1) gemm_lse_kernel() {
    extern __shared__ __align__(1024) char dsmem[];
    __shared__ __align__(8) uint64_t s_mbar[3];   // B0, B1, A

    const int tid = threadIdx.x;
    const int warp = tid >> 5;
    const int lane = tid & 31;

    uint32_t sb = smem_u32(dsmem);
    const uint32_t aBase = (sb + 1023u) & ~1023u;
    const uint32_t bBase[2] = {aBase + 65536u, aBase + 131072u};
    const uint32_t mbB[2] = {smem_u32(&s_mbar[0]), smem_u32(&s_mbar[1])};
    const uint32_t mbA = smem_u32(&s_mbar[2]);

    if (tid == 0) {
        MBAR_INIT(mbB[0], 1);
        MBAR_INIT(mbB[1], 1);
        MBAR_INIT(mbA, 1);
    }
    __syncthreads();

    const int t_begin = ((int)blockIdx.x * NTILES) / GRID;
    const int t_end = (((int)blockIdx.x + 1) * NTILES) / GRID;

    if (warp == 0 && elect_one()) {
        MBAR_EXPECT(mbA, 65536u);
        BULK_LD(aBase, (const char*)g_pk + (size_t)(t_begin >> 6) * 65536, 65536u, mbA);
        MBAR_EXPECT(mbB[0], 65536u);
        BULK_LD(bBase[0], (const char*)g_nv + (size_t)(t_begin & 63) * 65536, 65536u, mbB[0]);
    }

    const int arow = warp * 16 + (lane & 7) + ((lane >> 3) & 1) * 8;
    const uint32_t a_rx = (uint32_t)((arow & 7) << 4);
    const uint32_t a_rb = (uint32_t)(arow * 128);
    const uint32_t lnc = (uint32_t)((lane >> 4) << 4);
    uint32_t brb[8], brx[8];
    {
        const int nr = (lane & 7) + ((lane >> 3) & 1) * 8;
        #pragma unroll
        for (int j = 0; j < 8; j++) {
            int r = j * 16 + nr;
            brb[j] = (uint32_t)(r * 128);
            brx[j] = (uint32_t)((r & 7) << 4) ^ lnc;
        }
    }

    const __half2 Chh = __half2half2(__float2half(0.72134752044448170f));  // log2(e)/2
    const uint32_t Ch2 = *reinterpret_cast<const uint32_t*>(&Chh);

    uint32_t afr[16][4];
    uint32_t acc0[16][2], acc1[16][2];
    #pragma unroll
    for (int g = 0; g < 16; g++) {
        acc0[g][0] = acc0[g][1] = 0u;
        acc1[g][0] = acc1[g][1] = 0u;
    }

    int curRb = -1, phA = 0, prevRb = 0;

    for (int t = t_begin, k = 0; t < t_end; t++, k++) {
        const int rb = t >> 6;
        if (rb != curRb) {
            MBAR_WAIT(mbA, phA);
            phA ^= 1;
            #pragma unroll
            for (int ks = 0; ks < 16; ks++) {
                uint32_t addr = aBase + ((ks >> 2) << 14) + a_rb
                              + ((((uint32_t)(ks & 3) << 5) | lnc) ^ a_rx);
                asm volatile("ldmatrix.sync.aligned.m8n8.x4.shared.b16 {%0,%1,%2,%3},[%4];"
                             : "=r"(afr[ks][0]), "=r"(afr[ks][1]), "=r"(afr[ks][2]), "=r"(afr[ks][3])
                             : "r"(addr));
            }
            curRb = rb;
        }
        __syncthreads();   // all warps done with B[(k+1)&1] and A extraction

        const int tn = t + 1;
        if (tn < t_end && warp == 0 && elect_one()) {
            MBAR_EXPECT(mbB[(k + 1) & 1], 65536u);
            BULK_LD(bBase[(k + 1) & 1],
                    (const char*)g_nv + (size_t)(tn & 63) * 65536, 65536u, mbB[(k + 1) & 1]);
            if ((tn >> 6) != rb) {
                MBAR_EXPECT(mbA, 65536u);
                BULK_LD(aBase, (const char*)g_pk + (size_t)(tn >> 6) * 65536, 65536u, mbA);
            }
        }
        MBAR_WAIT(mbB[k & 1], (k >> 1) & 1);

        const uint32_t bb = bBase[k & 1];
        const bool doEpi = (k > 0);
        const int epiRow = prevRb * TILE + warp * 16 + (lane >> 2);
        if (k & 1)
            tile_body(bb, afr, brb, brx, acc1, acc0, doEpi, epiRow, lane, Ch2);
        else
            tile_body(bb, afr, brb, brx, acc0, acc1, doEpi, epiRow, lane, Ch2);
        prevRb = rb;
    }

    // epilogue for the final tile
    const int epiRow = prevRb * TILE + warp * 16 + (lane >> 2);
    if ((t_end - t_begin - 1) & 1)
        epi_only(acc1, epiRow, lane, Ch2);
    else
        epi_only(acc0, epiRow, lane, Ch2);
}

// ---------------------------------------------------------------------------
// Kernel 3: parallel final reduction (R11-exact).
// ---------------------------------------------------------------------------
__global__ void __launch_bounds__(256) reduce_kernel(float* __restrict__ out) {
    __shared__ float sv[8];
    const int tid = threadIdx.x;
    const int r = blockIdx.x * 256 + tid;
    float v = __logf(g_rowsum[r]) - 0.5f * g_pos[r];
    #pragma unroll
    for (int o = 16; o > 0; o >>= 1)
        v += __shfl_xor_sync(0xffffffffu, v, o);
    const int lane = tid & 31, warp = tid >> 5;
    if (lane == 0) sv[warp] = v;
    __syncthreads();
    if (warp == 0) {
        v = (lane < 8) ? sv[lane] : 0.0f;
        #pragma unroll
        for (int o = 4; o > 0; o >>= 1)
            v += __shfl_xor_sync(0xffffffffu, v, o);
        if (lane == 0)
            atomicAdd(out, v * (1.0f / NROW));
    }
}

// ---------------------------------------------------------------------------
extern "C" void kernel_launch(void* const* d_in, const int* in_sizes, int n_in,
                              void* d_out, int out_size) {
    const float* pk = reinterpret_cast<const float*>(d_in[0]);
    const float* pv = reinterpret_cast<const float*>(d_in[1]);
    const float* nv = reinterpret_cast<const float*>(d_in[2]);
    float* out = reinterpret_cast<float*>(d_out);

    const int smem_bytes = 1024 + 3 * 65536;  // pad + A + 2x B
    cudaFuncSetAttribute(gemm_lse_kernel,
                         cudaFuncAttributeMaxDynamicSharedMemorySize, smem_bytes);

    prep_kernel<<<(NROW + MROW) / 16, 256>>>(pk, pv, nv, out);
    gemm_lse_kernel<<<GRID, 256, smem_bytes>>>();
    reduce_kernel<<<32, 256>>>(out);
}